// round 15
// baseline (speedup 1.0000x reference)
#include <cuda_runtime.h>
#include <cuda_bf16.h>
#include <math.h>
#include <stdint.h>

// ============================ problem dims =================================
#define M_ROWS 16384
#define K_DIM  4096
#define N_DIM  4096

// ============================ GEMM tiling ==================================
#define BM 128
#define BN 128
#define BK 32                       // bf16 per k-chunk -> 64B rows in smem
#define KIT (K_DIM / BK)            // 128 k-iterations
#define NSPLIT 2
#define NSTAGES 4

#define TILE_BYTES (128 * 64)       // 8 KB: 128 rows x 32 bf16
#define STAGE_BYTES (3 * TILE_BYTES)        // 2 A-split tiles + 1 B tile = 24 KB
#define SMEM_TILES_OFF 1024
#define DYN_SMEM (SMEM_TILES_OFF + NSTAGES * STAGE_BYTES)   // ~97 KB -> 2 CTAs/SM

// Marginal threshold: |h_tc| < DELTA -> recompute with sequential fp32.
// sigma(|h_tc - h_seq|) ~ 3e-4 (fp32 ordering + 2-split residual); 0.006 = 20 sigma.
#define DELTA 0.006f
#define MAXW  (4u * 1024u * 1024u)

// ============================ device scratch ===============================
__device__ float g_s[M_ROWS];
__device__ unsigned int g_cnt;
__device__ unsigned int g_wl[MAXW];   // packed: sign<<31 | m*4096 + n
__device__ __nv_bfloat16 g_X0[(size_t)M_ROWS * K_DIM];
__device__ __nv_bfloat16 g_X1[(size_t)M_ROWS * K_DIM];
__device__ __nv_bfloat16 g_Wb[(size_t)N_DIM * K_DIM];     // sign(W1) as bf16 +/-1

// ============================ PTX helpers ==================================
__device__ __forceinline__ uint32_t smem_u32(const void* p) {
    uint32_t a;
    asm("{ .reg .u64 t; cvta.to.shared.u64 t, %1; cvt.u32.u64 %0, t; }"
        : "=r"(a) : "l"(p));
    return a;
}

#define CP_ASYNC16(dst, src) \
    asm volatile("cp.async.cg.shared.global [%0], [%1], 16;" \
                 :: "r"(dst), "l"(src) : "memory")
#define CP_COMMIT() asm volatile("cp.async.commit_group;" ::: "memory")
#define CP_WAIT2()  asm volatile("cp.async.wait_group 2;" ::: "memory")

__device__ __forceinline__ void ldm_x4(uint32_t* r, uint32_t addr) {
    asm volatile("ldmatrix.sync.aligned.m8n8.x4.shared.b16 {%0,%1,%2,%3}, [%4];"
                 : "=r"(r[0]), "=r"(r[1]), "=r"(r[2]), "=r"(r[3]) : "r"(addr));
}

__device__ __forceinline__ void mma_bf16(float* c, const uint32_t* a,
                                         const uint32_t* b) {
    asm volatile(
        "mma.sync.aligned.m16n8k16.row.col.f32.bf16.bf16.f32 "
        "{%0,%1,%2,%3}, {%4,%5,%6,%7}, {%8,%9}, {%0,%1,%2,%3};"
        : "+f"(c[0]), "+f"(c[1]), "+f"(c[2]), "+f"(c[3])
        : "r"(a[0]), "r"(a[1]), "r"(a[2]), "r"(a[3]), "r"(b[0]), "r"(b[1]));
}

// smem tile addressing: 128 rows x 64B, 4x 16B chunks/row, swizzled.
__device__ __forceinline__ uint32_t swz(uint32_t base, int row, int chunk) {
    return base + row * 64 + ((chunk ^ ((row >> 1) & 3)) << 4);
}

// ============================ prepass kernels ==============================
// binarize_w1 also zeroes g_s / g_cnt (524K threads cover 16K rows for free).
__global__ void binarize_w1_kernel(const float* __restrict__ W1) {
    size_t id = (size_t)blockIdx.x * blockDim.x + threadIdx.x;
    if (id < M_ROWS) g_s[id] = 0.0f;
    if (id == 0) g_cnt = 0u;

    size_t i = id * 8;
    float4 v0 = *reinterpret_cast<const float4*>(W1 + i);
    float4 v1 = *reinterpret_cast<const float4*>(W1 + i + 4);
    const unsigned short P = 0x3F80, N = 0xBF80;   // bf16 +1 / -1
    ushort4 oa, ob;
    oa.x = (v0.x >= 0.f) ? P : N;  oa.y = (v0.y >= 0.f) ? P : N;
    oa.z = (v0.z >= 0.f) ? P : N;  oa.w = (v0.w >= 0.f) ? P : N;
    ob.x = (v1.x >= 0.f) ? P : N;  ob.y = (v1.y >= 0.f) ? P : N;
    ob.z = (v1.z >= 0.f) ? P : N;  ob.w = (v1.w >= 0.f) ? P : N;
    uint4 o;
    o.x = ((uint32_t)oa.y << 16) | oa.x;
    o.y = ((uint32_t)oa.w << 16) | oa.z;
    o.z = ((uint32_t)ob.y << 16) | ob.x;
    o.w = ((uint32_t)ob.w << 16) | ob.z;
    *reinterpret_cast<uint4*>(&g_Wb[i]) = o;
}

// 2-way bf16 split, 8 elems/thread with 16B stores per plane.
// x ~ b0+b1, residual <= 2^-17 |x|; products with +/-1 are exact, so
// |h_tc - h_seq| sigma ~3e-4 << DELTA; correction fixes all signs.
__global__ void split_x_kernel(const float* __restrict__ X) {
    size_t i = ((size_t)blockIdx.x * blockDim.x + threadIdx.x) * 8;
    float4 v0 = *reinterpret_cast<const float4*>(X + i);
    float4 v1 = *reinterpret_cast<const float4*>(X + i + 4);
    float f[8] = {v0.x, v0.y, v0.z, v0.w, v1.x, v1.y, v1.z, v1.w};
    unsigned short p0[8], p1[8];
#pragma unroll
    for (int j = 0; j < 8; ++j) {
        float x = f[j];
        __nv_bfloat16 b0 = __float2bfloat16(x);
        float r1 = x - __bfloat162float(b0);
        __nv_bfloat16 b1 = __float2bfloat16(r1);
        p0[j] = __bfloat16_as_ushort(b0);
        p1[j] = __bfloat16_as_ushort(b1);
    }
    uint4 o0, o1;
    o0.x = ((uint32_t)p0[1] << 16) | p0[0];
    o0.y = ((uint32_t)p0[3] << 16) | p0[2];
    o0.z = ((uint32_t)p0[5] << 16) | p0[4];
    o0.w = ((uint32_t)p0[7] << 16) | p0[6];
    o1.x = ((uint32_t)p1[1] << 16) | p1[0];
    o1.y = ((uint32_t)p1[3] << 16) | p1[2];
    o1.z = ((uint32_t)p1[5] << 16) | p1[4];
    o1.w = ((uint32_t)p1[7] << 16) | p1[6];
    *reinterpret_cast<uint4*>(&g_X0[i]) = o0;
    *reinterpret_cast<uint4*>(&g_X1[i]) = o1;
}

// ============================ main GEMM (tensor) ===========================
// 8 warps (4m x 2n), warp tile 32x64, mma.sync m16n8k16 bf16, 4-stage
// cp.async pipeline, 2 CTAs/SM, single barrier per k-iteration, unroll x4.
// Round-13 schedule (local optimum at 128 regs): front-loaded ks-half frag
// groups, cp.async block placed to hide the ks=0 LDSM latency.
__global__ __launch_bounds__(256, 2)
void gemm_mma_kernel(const float* __restrict__ W2) {
    extern __shared__ char dsm[];
    const uint32_t sb = smem_u32(dsm);
    float* w2s = reinterpret_cast<float*>(dsm);          // [128]
    const uint32_t tiles = sb + SMEM_TILES_OFF;

    const int tid  = threadIdx.x;
    const int wid  = tid >> 5;
    const int lane = tid & 31;
    const int WM   = (wid >> 1) * 32;
    const int WN   = (wid & 1) * 64;

    // Supertiled CTA order: 8 m-blocks x 32 n-blocks per supertile.
    const int bid = blockIdx.x;
    const int sid = bid >> 8;
    const int rem = bid & 255;
    const int bm  = (sid * 8 + (rem & 7)) * BM;
    const int bn  = (rem >> 3) * BN;

    if (tid < BN) w2s[tid] = (W2[bn + tid] >= 0.f) ? 1.f : -1.f;

    const __nv_bfloat16* abase[NSPLIT] = {
        g_X0 + (size_t)bm * K_DIM,
        g_X1 + (size_t)bm * K_DIM };
    const __nv_bfloat16* bbase = g_Wb + (size_t)bn * K_DIM;

#define LOAD_STAGE(stg, kt) do {                                              \
    const int _k0 = (kt) * BK;                                                \
    const uint32_t _sb0 = tiles + (stg) * STAGE_BYTES;                        \
    _Pragma("unroll")                                                         \
    for (int _t = 0; _t < 3; ++_t) {                                          \
        const __nv_bfloat16* _g = (_t < 2) ? abase[_t] : bbase;               \
        const uint32_t _tb = _sb0 + _t * TILE_BYTES;                          \
        _Pragma("unroll")                                                     \
        for (int _j = 0; _j < 2; ++_j) {                                      \
            int _id  = tid + _j * 256;                                        \
            int _row = _id >> 2;                                              \
            int _c   = _id & 3;                                               \
            CP_ASYNC16(swz(_tb, _row, _c),                                    \
                       _g + (size_t)_row * K_DIM + _k0 + _c * 8);             \
        }                                                                     \
    }                                                                         \
    CP_COMMIT();                                                              \
} while (0)

    LOAD_STAGE(0, 0);
    LOAD_STAGE(1, 1);
    LOAD_STAGE(2, 2);

    float acc[2][8][4];
#pragma unroll
    for (int mi = 0; mi < 2; ++mi)
#pragma unroll
        for (int ni = 0; ni < 8; ++ni)
#pragma unroll
            for (int e = 0; e < 4; ++e) acc[mi][ni][e] = 0.f;

    const int arow  = WM + (lane & 7) + ((lane >> 3) & 1) * 8;
    const int achk  = lane >> 4;
    const int brow0 = WN + (lane & 7) + ((lane >> 4) & 1) * 8;
    const int bchk  = (lane >> 3) & 1;

    // Fragment loads for one ks-half: 4 B + 2+2 A (both planes) = 8 ldmatrix.
#define LOAD_FRAGS(s0, bt, ks, br, ar)  do {                                  \
    _Pragma("unroll")                                                         \
    for (int gi = 0; gi < 4; ++gi)                                            \
        ldm_x4(&(br)[gi * 4], swz((bt), brow0 + gi * 16, 2 * (ks) + bchk));   \
    _Pragma("unroll")                                                         \
    for (int p = 0; p < NSPLIT; ++p) {                                        \
        const uint32_t _at = (s0) + p * TILE_BYTES;                           \
        ldm_x4(&(ar)[p * 8],     swz(_at, arow,      2 * (ks) + achk));       \
        ldm_x4(&(ar)[p * 8 + 4], swz(_at, arow + 16, 2 * (ks) + achk));       \
    }                                                                         \
} while (0)

    // All 32 MMAs for one ks-half (both planes).
#define DO_MMAS(br, ar) do {                                                  \
    _Pragma("unroll")                                                         \
    for (int p = 0; p < NSPLIT; ++p)                                          \
        _Pragma("unroll")                                                     \
        for (int mi = 0; mi < 2; ++mi)                                        \
            _Pragma("unroll")                                                 \
            for (int ni = 0; ni < 8; ++ni)                                    \
                mma_bf16(acc[mi][ni], &(ar)[p * 8 + mi * 4],                  \
                         &(br)[(ni >> 1) * 4 + (ni & 1) * 2]);                \
} while (0)

    // One k-iteration: barrier, front-loaded ks=0 fragment loads, cp.async
    // block (hides LDSM latency), ks=0 MMAs, ks=1 loads, ks=1 MMAs.
#define K_ITER(it) do {                                                       \
    CP_WAIT2();                                                               \
    __syncthreads();                                                          \
    const uint32_t s0 = tiles + ((it) & 3) * STAGE_BYTES;                     \
    const uint32_t bt = s0 + 2 * TILE_BYTES;                                  \
    uint32_t br[16], ar[16];                                                  \
    LOAD_FRAGS(s0, bt, 0, br, ar);                                            \
    if ((it) + 3 < KIT) LOAD_STAGE(((it) + 3) & 3, (it) + 3);                 \
    else                CP_COMMIT();                                          \
    DO_MMAS(br, ar);                                                          \
    LOAD_FRAGS(s0, bt, 1, br, ar);                                            \
    DO_MMAS(br, ar);                                                          \
} while (0)

    // Unroll x4 over k-iterations (KIT % 4 == 0).
    for (int it = 0; it < KIT; it += 4) {
        K_ITER(it);
        K_ITER(it + 1);
        K_ITER(it + 2);
        K_ITER(it + 3);
    }

    // --------------------------- epilogue ----------------------------------
    // acc[mi][ni][e]: m = WM + mi*16 + (lane>>2) + (e>=2)*8
    //                 n = WN + ni*8 + (lane&3)*2 + (e&1)
    float rs[2][2] = {{0.f, 0.f}, {0.f, 0.f}};
#pragma unroll
    for (int mi = 0; mi < 2; ++mi)
#pragma unroll
        for (int ni = 0; ni < 8; ++ni)
#pragma unroll
            for (int e = 0; e < 4; ++e) {
                float h = acc[mi][ni][e];
                int nl = WN + ni * 8 + (lane & 3) * 2 + (e & 1);
                float w = w2s[nl];
                bool pos = (h >= 0.f);
                rs[mi][e >> 1] += pos ? w : -w;
                if (fabsf(h) < DELTA) {   // marginal: queue fp32 recheck
                    int m = bm + WM + mi * 16 + (lane >> 2) + (e >> 1) * 8;
                    unsigned idx = atomicAdd(&g_cnt, 1u);
                    if (idx < MAXW)
                        g_wl[idx] = (unsigned)(m * 4096 + (bn + nl)) |
                                    (pos ? 0x80000000u : 0u);
                }
            }

#pragma unroll
    for (int mi = 0; mi < 2; ++mi)
#pragma unroll
        for (int eh = 0; eh < 2; ++eh) {
            rs[mi][eh] += __shfl_xor_sync(0xffffffffu, rs[mi][eh], 1);
            rs[mi][eh] += __shfl_xor_sync(0xffffffffu, rs[mi][eh], 2);
        }

    if ((lane & 3) == 0) {
#pragma unroll
        for (int mi = 0; mi < 2; ++mi)
#pragma unroll
            for (int eh = 0; eh < 2; ++eh) {
                int m = bm + WM + mi * 16 + (lane >> 2) + eh * 8;
                atomicAdd(&g_s[m], rs[mi][eh]);
            }
    }
#undef K_ITER
#undef DO_MMAS
#undef LOAD_FRAGS
#undef LOAD_STAGE
}

// ===================== correction: sequential fp32 recheck =================
// Recompute marginal h with a strictly k-ascending single-accumulator fp32
// FMA chain (round-1 arithmetic, matches the reference rounding class).
// Apply +/-2*w2 delta on sign flip; deltas additive -> order-independent.
__global__ void correction_kernel(const float* __restrict__ X,
                                  const float* __restrict__ W1,
                                  const float* __restrict__ W2) {
    unsigned cnt = g_cnt;
    if (cnt > MAXW) cnt = MAXW;
    for (unsigned i = blockIdx.x * blockDim.x + threadIdx.x; i < cnt;
         i += gridDim.x * blockDim.x) {
        unsigned e = g_wl[i];
        bool sign_tc = (e >> 31) != 0u;
        unsigned v = e & 0x7FFFFFFFu;
        int m = (int)(v >> 12);
        int n = (int)(v & 4095u);
        const float* xr = X  + (size_t)m * K_DIM;
        const float* wr = W1 + (size_t)n * K_DIM;
        float acc = 0.f;
        for (int k = 0; k < K_DIM; k += 4) {
            float4 xv = *reinterpret_cast<const float4*>(xr + k);
            float4 wv = *reinterpret_cast<const float4*>(wr + k);
            acc = fmaf(xv.x, (wv.x >= 0.f) ? 1.f : -1.f, acc);
            acc = fmaf(xv.y, (wv.y >= 0.f) ? 1.f : -1.f, acc);
            acc = fmaf(xv.z, (wv.z >= 0.f) ? 1.f : -1.f, acc);
            acc = fmaf(xv.w, (wv.w >= 0.f) ? 1.f : -1.f, acc);
        }
        bool sign_seq = (acc >= 0.f);
        if (sign_seq != sign_tc) {
            float w = (W2[n] >= 0.f) ? 1.f : -1.f;
            atomicAdd(&g_s[m], sign_seq ? 2.f * w : -2.f * w);
        }
    }
}

// ============================ finalize =====================================
__global__ void finalize_kernel(float* __restrict__ out, int out_size) {
    int b = blockIdx.x * blockDim.x + threadIdx.x;
    if (b >= M_ROWS) return;
    float s = g_s[b];
    float o = 1.0f / (1.0f + expf(-s));
    if (b < out_size) out[b] = o;
    int yi = M_ROWS + b;
    if (yi < out_size) out[yi] = (s >= 0.0f) ? 1.0f : 0.0f;
}

// ============================ launcher =====================================
extern "C" void kernel_launch(void* const* d_in, const int* in_sizes, int n_in,
                              void* d_out, int out_size) {
    const float* X  = (const float*)d_in[0];   // [16384, 4096]
    const float* W1 = (const float*)d_in[1];   // [4096, 4096]
    const float* W2 = (const float*)d_in[2];   // [4096]
    float* out = (float*)d_out;

    cudaFuncSetAttribute(gemm_mma_kernel,
                         cudaFuncAttributeMaxDynamicSharedMemorySize, DYN_SMEM);

    binarize_w1_kernel<<<(N_DIM * (size_t)K_DIM) / (8 * 256), 256>>>(W1);
    split_x_kernel<<<(M_ROWS * (size_t)K_DIM) / (8 * 256), 256>>>(X);

    gemm_mma_kernel<<<(M_ROWS / BM) * (N_DIM / BN), 256, DYN_SMEM>>>(W2);

    correction_kernel<<<256, 128>>>(X, W1, W2);

    finalize_kernel<<<(M_ROWS + 255) / 256, 256>>>(out, out_size);
}

// round 16
// speedup vs baseline: 1.0873x; 1.0873x over previous
#include <cuda_runtime.h>
#include <cuda_bf16.h>
#include <math.h>
#include <stdint.h>

// ============================ problem dims =================================
#define M_ROWS 16384
#define K_DIM  4096
#define N_DIM  4096

// ============================ GEMM tiling ==================================
#define BM 128
#define BN 128
#define BK 32                       // bf16 per k-chunk -> 64B rows in smem
#define KIT (K_DIM / BK)            // 128 k-iterations
#define NSPLIT 2
#define NSTAGES 4

#define TILE_BYTES (128 * 64)       // 8 KB: 128 rows x 32 bf16
#define STAGE_BYTES (3 * TILE_BYTES)        // 2 A-split tiles + 1 B tile = 24 KB
#define SMEM_TILES_OFF 1024
#define DYN_SMEM (SMEM_TILES_OFF + NSTAGES * STAGE_BYTES)   // ~97 KB -> 2 CTAs/SM

// Marginal threshold: |h_tc| < DELTA -> recompute with sequential fp32.
// sigma(|h_tc - h_seq|) ~ 3e-4 (fp32 ordering + 2-split residual); 0.006 = 20 sigma.
#define DELTA 0.006f
#define MAXW  (4u * 1024u * 1024u)

// ============================ device scratch ===============================
__device__ float g_s[M_ROWS];
__device__ unsigned int g_cnt;
__device__ unsigned int g_wl[MAXW];   // packed: sign<<31 | m*4096 + n
__device__ __nv_bfloat16 g_X0[(size_t)M_ROWS * K_DIM];
__device__ __nv_bfloat16 g_X1[(size_t)M_ROWS * K_DIM];
__device__ __nv_bfloat16 g_Wb[(size_t)N_DIM * K_DIM];     // sign(W1) as bf16 +/-1

// ============================ PTX helpers ==================================
__device__ __forceinline__ uint32_t smem_u32(const void* p) {
    uint32_t a;
    asm("{ .reg .u64 t; cvta.to.shared.u64 t, %1; cvt.u32.u64 %0, t; }"
        : "=r"(a) : "l"(p));
    return a;
}

#define CP_ASYNC16(dst, src) \
    asm volatile("cp.async.cg.shared.global [%0], [%1], 16;" \
                 :: "r"(dst), "l"(src) : "memory")
#define CP_COMMIT() asm volatile("cp.async.commit_group;" ::: "memory")
#define CP_WAIT2()  asm volatile("cp.async.wait_group 2;" ::: "memory")

__device__ __forceinline__ void ldm_x4(uint32_t* r, uint32_t addr) {
    asm volatile("ldmatrix.sync.aligned.m8n8.x4.shared.b16 {%0,%1,%2,%3}, [%4];"
                 : "=r"(r[0]), "=r"(r[1]), "=r"(r[2]), "=r"(r[3]) : "r"(addr));
}

__device__ __forceinline__ void mma_bf16(float* c, const uint32_t* a,
                                         const uint32_t* b) {
    asm volatile(
        "mma.sync.aligned.m16n8k16.row.col.f32.bf16.bf16.f32 "
        "{%0,%1,%2,%3}, {%4,%5,%6,%7}, {%8,%9}, {%0,%1,%2,%3};"
        : "+f"(c[0]), "+f"(c[1]), "+f"(c[2]), "+f"(c[3])
        : "r"(a[0]), "r"(a[1]), "r"(a[2]), "r"(a[3]), "r"(b[0]), "r"(b[1]));
}

// smem tile addressing: 128 rows x 64B, 4x 16B chunks/row, swizzled.
__device__ __forceinline__ uint32_t swz(uint32_t base, int row, int chunk) {
    return base + row * 64 + ((chunk ^ ((row >> 1) & 3)) << 4);
}

// ============================ prepass kernels ==============================
// binarize_w1 also zeroes g_s / g_cnt (524K threads cover 16K rows for free).
__global__ void binarize_w1_kernel(const float* __restrict__ W1) {
    size_t id = (size_t)blockIdx.x * blockDim.x + threadIdx.x;
    if (id < M_ROWS) g_s[id] = 0.0f;
    if (id == 0) g_cnt = 0u;

    size_t i = id * 8;
    float4 v0 = *reinterpret_cast<const float4*>(W1 + i);
    float4 v1 = *reinterpret_cast<const float4*>(W1 + i + 4);
    const unsigned short P = 0x3F80, N = 0xBF80;   // bf16 +1 / -1
    ushort4 oa, ob;
    oa.x = (v0.x >= 0.f) ? P : N;  oa.y = (v0.y >= 0.f) ? P : N;
    oa.z = (v0.z >= 0.f) ? P : N;  oa.w = (v0.w >= 0.f) ? P : N;
    ob.x = (v1.x >= 0.f) ? P : N;  ob.y = (v1.y >= 0.f) ? P : N;
    ob.z = (v1.z >= 0.f) ? P : N;  ob.w = (v1.w >= 0.f) ? P : N;
    uint4 o;
    o.x = ((uint32_t)oa.y << 16) | oa.x;
    o.y = ((uint32_t)oa.w << 16) | oa.z;
    o.z = ((uint32_t)ob.y << 16) | ob.x;
    o.w = ((uint32_t)ob.w << 16) | ob.z;
    *reinterpret_cast<uint4*>(&g_Wb[i]) = o;
}

// 2-way bf16 split, 8 elems/thread with 16B stores per plane.
// x ~ b0+b1, residual <= 2^-17 |x|; products with +/-1 are exact, so
// |h_tc - h_seq| sigma ~3e-4 << DELTA; correction fixes all signs.
__global__ void split_x_kernel(const float* __restrict__ X) {
    size_t i = ((size_t)blockIdx.x * blockDim.x + threadIdx.x) * 8;
    float4 v0 = *reinterpret_cast<const float4*>(X + i);
    float4 v1 = *reinterpret_cast<const float4*>(X + i + 4);
    float f[8] = {v0.x, v0.y, v0.z, v0.w, v1.x, v1.y, v1.z, v1.w};
    unsigned short p0[8], p1[8];
#pragma unroll
    for (int j = 0; j < 8; ++j) {
        float x = f[j];
        __nv_bfloat16 b0 = __float2bfloat16(x);
        float r1 = x - __bfloat162float(b0);
        __nv_bfloat16 b1 = __float2bfloat16(r1);
        p0[j] = __bfloat16_as_ushort(b0);
        p1[j] = __bfloat16_as_ushort(b1);
    }
    uint4 o0, o1;
    o0.x = ((uint32_t)p0[1] << 16) | p0[0];
    o0.y = ((uint32_t)p0[3] << 16) | p0[2];
    o0.z = ((uint32_t)p0[5] << 16) | p0[4];
    o0.w = ((uint32_t)p0[7] << 16) | p0[6];
    o1.x = ((uint32_t)p1[1] << 16) | p1[0];
    o1.y = ((uint32_t)p1[3] << 16) | p1[2];
    o1.z = ((uint32_t)p1[5] << 16) | p1[4];
    o1.w = ((uint32_t)p1[7] << 16) | p1[6];
    *reinterpret_cast<uint4*>(&g_X0[i]) = o0;
    *reinterpret_cast<uint4*>(&g_X1[i]) = o1;
}

// ============================ main GEMM (tensor) ===========================
// 8 warps (4m x 2n), warp tile 32x64, mma.sync m16n8k16 bf16, 4-stage
// cp.async pipeline, 2 CTAs/SM, single barrier per k-iteration, unroll x4.
// Round-13 schedule (local optimum at 128 regs): front-loaded ks-half frag
// groups, cp.async block placed to hide the ks=0 LDSM latency.
__global__ __launch_bounds__(256, 2)
void gemm_mma_kernel(const float* __restrict__ W2) {
    extern __shared__ char dsm[];
    const uint32_t sb = smem_u32(dsm);
    float* w2s = reinterpret_cast<float*>(dsm);          // [128]
    const uint32_t tiles = sb + SMEM_TILES_OFF;

    const int tid  = threadIdx.x;
    const int wid  = tid >> 5;
    const int lane = tid & 31;
    const int WM   = (wid >> 1) * 32;
    const int WN   = (wid & 1) * 64;

    // Supertiled CTA order: 8 m-blocks x 32 n-blocks per supertile.
    const int bid = blockIdx.x;
    const int sid = bid >> 8;
    const int rem = bid & 255;
    const int bm  = (sid * 8 + (rem & 7)) * BM;
    const int bn  = (rem >> 3) * BN;

    if (tid < BN) w2s[tid] = (W2[bn + tid] >= 0.f) ? 1.f : -1.f;

    const __nv_bfloat16* abase[NSPLIT] = {
        g_X0 + (size_t)bm * K_DIM,
        g_X1 + (size_t)bm * K_DIM };
    const __nv_bfloat16* bbase = g_Wb + (size_t)bn * K_DIM;

#define LOAD_STAGE(stg, kt) do {                                              \
    const int _k0 = (kt) * BK;                                                \
    const uint32_t _sb0 = tiles + (stg) * STAGE_BYTES;                        \
    _Pragma("unroll")                                                         \
    for (int _t = 0; _t < 3; ++_t) {                                          \
        const __nv_bfloat16* _g = (_t < 2) ? abase[_t] : bbase;               \
        const uint32_t _tb = _sb0 + _t * TILE_BYTES;                          \
        _Pragma("unroll")                                                     \
        for (int _j = 0; _j < 2; ++_j) {                                      \
            int _id  = tid + _j * 256;                                        \
            int _row = _id >> 2;                                              \
            int _c   = _id & 3;                                               \
            CP_ASYNC16(swz(_tb, _row, _c),                                    \
                       _g + (size_t)_row * K_DIM + _k0 + _c * 8);             \
        }                                                                     \
    }                                                                         \
    CP_COMMIT();                                                              \
} while (0)

    LOAD_STAGE(0, 0);
    LOAD_STAGE(1, 1);
    LOAD_STAGE(2, 2);

    float acc[2][8][4];
#pragma unroll
    for (int mi = 0; mi < 2; ++mi)
#pragma unroll
        for (int ni = 0; ni < 8; ++ni)
#pragma unroll
            for (int e = 0; e < 4; ++e) acc[mi][ni][e] = 0.f;

    const int arow  = WM + (lane & 7) + ((lane >> 3) & 1) * 8;
    const int achk  = lane >> 4;
    const int brow0 = WN + (lane & 7) + ((lane >> 4) & 1) * 8;
    const int bchk  = (lane >> 3) & 1;

    // Fragment loads for one ks-half: 4 B + 2+2 A (both planes) = 8 ldmatrix.
#define LOAD_FRAGS(s0, bt, ks, br, ar)  do {                                  \
    _Pragma("unroll")                                                         \
    for (int gi = 0; gi < 4; ++gi)                                            \
        ldm_x4(&(br)[gi * 4], swz((bt), brow0 + gi * 16, 2 * (ks) + bchk));   \
    _Pragma("unroll")                                                         \
    for (int p = 0; p < NSPLIT; ++p) {                                        \
        const uint32_t _at = (s0) + p * TILE_BYTES;                           \
        ldm_x4(&(ar)[p * 8],     swz(_at, arow,      2 * (ks) + achk));       \
        ldm_x4(&(ar)[p * 8 + 4], swz(_at, arow + 16, 2 * (ks) + achk));       \
    }                                                                         \
} while (0)

    // All 32 MMAs for one ks-half (both planes).
#define DO_MMAS(br, ar) do {                                                  \
    _Pragma("unroll")                                                         \
    for (int p = 0; p < NSPLIT; ++p)                                          \
        _Pragma("unroll")                                                     \
        for (int mi = 0; mi < 2; ++mi)                                        \
            _Pragma("unroll")                                                 \
            for (int ni = 0; ni < 8; ++ni)                                    \
                mma_bf16(acc[mi][ni], &(ar)[p * 8 + mi * 4],                  \
                         &(br)[(ni >> 1) * 4 + (ni & 1) * 2]);                \
} while (0)

    // One k-iteration: barrier, front-loaded ks=0 fragment loads, cp.async
    // block (hides LDSM latency), ks=0 MMAs, ks=1 loads, ks=1 MMAs.
#define K_ITER(it) do {                                                       \
    CP_WAIT2();                                                               \
    __syncthreads();                                                          \
    const uint32_t s0 = tiles + ((it) & 3) * STAGE_BYTES;                     \
    const uint32_t bt = s0 + 2 * TILE_BYTES;                                  \
    uint32_t br[16], ar[16];                                                  \
    LOAD_FRAGS(s0, bt, 0, br, ar);                                            \
    if ((it) + 3 < KIT) LOAD_STAGE(((it) + 3) & 3, (it) + 3);                 \
    else                CP_COMMIT();                                          \
    DO_MMAS(br, ar);                                                          \
    LOAD_FRAGS(s0, bt, 1, br, ar);                                            \
    DO_MMAS(br, ar);                                                          \
} while (0)

    // Unroll x4 over k-iterations (KIT % 4 == 0).
    for (int it = 0; it < KIT; it += 4) {
        K_ITER(it);
        K_ITER(it + 1);
        K_ITER(it + 2);
        K_ITER(it + 3);
    }

    // --------------------------- epilogue ----------------------------------
    // acc[mi][ni][e]: m = WM + mi*16 + (lane>>2) + (e>=2)*8
    //                 n = WN + ni*8 + (lane&3)*2 + (e&1)
    float rs[2][2] = {{0.f, 0.f}, {0.f, 0.f}};
#pragma unroll
    for (int mi = 0; mi < 2; ++mi)
#pragma unroll
        for (int ni = 0; ni < 8; ++ni)
#pragma unroll
            for (int e = 0; e < 4; ++e) {
                float h = acc[mi][ni][e];
                int nl = WN + ni * 8 + (lane & 3) * 2 + (e & 1);
                float w = w2s[nl];
                bool pos = (h >= 0.f);
                rs[mi][e >> 1] += pos ? w : -w;
                if (fabsf(h) < DELTA) {   // marginal: queue fp32 recheck
                    int m = bm + WM + mi * 16 + (lane >> 2) + (e >> 1) * 8;
                    unsigned idx = atomicAdd(&g_cnt, 1u);
                    if (idx < MAXW)
                        g_wl[idx] = (unsigned)(m * 4096 + (bn + nl)) |
                                    (pos ? 0x80000000u : 0u);
                }
            }

#pragma unroll
    for (int mi = 0; mi < 2; ++mi)
#pragma unroll
        for (int eh = 0; eh < 2; ++eh) {
            rs[mi][eh] += __shfl_xor_sync(0xffffffffu, rs[mi][eh], 1);
            rs[mi][eh] += __shfl_xor_sync(0xffffffffu, rs[mi][eh], 2);
        }

    if ((lane & 3) == 0) {
#pragma unroll
        for (int mi = 0; mi < 2; ++mi)
#pragma unroll
            for (int eh = 0; eh < 2; ++eh) {
                int m = bm + WM + mi * 16 + (lane >> 2) + eh * 8;
                atomicAdd(&g_s[m], rs[mi][eh]);
            }
    }
#undef K_ITER
#undef DO_MMAS
#undef LOAD_FRAGS
#undef LOAD_STAGE
}

// ===================== correction: warp-cooperative recheck ================
// One WARP per marginal entry. The warp coalesced-loads 1024-element chunks
// of t[k] = sign(w1[n][k]) * x[m][k] into smem (negation is exact), then
// lane 0 alone performs the strictly k-ascending sum acc += t[k] -- which is
// bit-identical to the previous fmaf(x, +/-1, acc) chain (fma by +/-1 is a
// single-rounded add of +/-x). Loads get full warp MLP; only the 4096-add
// serial chain (~16K cyc) remains per entry, fully parallel across entries.
#define CCHUNK 1024

__global__ void correction_kernel(const float* __restrict__ X,
                                  const float* __restrict__ W1,
                                  const float* __restrict__ W2) {
    __shared__ float buf[4][CCHUNK];
    unsigned cnt = g_cnt;
    if (cnt > MAXW) cnt = MAXW;

    const int wid  = threadIdx.x >> 5;
    const int lane = threadIdx.x & 31;
    const unsigned gw = blockIdx.x * 4 + wid;
    const unsigned nw = gridDim.x * 4;

    for (unsigned i = gw; i < cnt; i += nw) {
        unsigned e = g_wl[i];
        bool sign_tc = (e >> 31) != 0u;
        unsigned v = e & 0x7FFFFFFFu;
        int m = (int)(v >> 12);
        int n = (int)(v & 4095u);
        const float* xr = X  + (size_t)m * K_DIM;
        const float* wr = W1 + (size_t)n * K_DIM;

        float acc = 0.f;
        for (int c = 0; c < K_DIM; c += CCHUNK) {
            // Warp loads CCHUNK elements: 8 float4 per lane, coalesced.
#pragma unroll
            for (int j = 0; j < CCHUNK / 128; ++j) {
                int o = (j * 32 + lane) * 4;           // chunk-local offset
                float4 xv = *reinterpret_cast<const float4*>(xr + c + o);
                float4 wv = *reinterpret_cast<const float4*>(wr + c + o);
                float4 t;
                t.x = (wv.x >= 0.f) ? xv.x : -xv.x;
                t.y = (wv.y >= 0.f) ? xv.y : -xv.y;
                t.z = (wv.z >= 0.f) ? xv.z : -xv.z;
                t.w = (wv.w >= 0.f) ? xv.w : -xv.w;
                *reinterpret_cast<float4*>(&buf[wid][o]) = t;
            }
            __syncwarp();
            if (lane == 0) {
#pragma unroll 16
                for (int k = 0; k < CCHUNK; ++k)
                    acc += buf[wid][k];                 // k-ascending, exact order
            }
            __syncwarp();
        }

        if (lane == 0) {
            bool sign_seq = (acc >= 0.f);
            if (sign_seq != sign_tc) {
                float w = (W2[n] >= 0.f) ? 1.f : -1.f;
                atomicAdd(&g_s[m], sign_seq ? 2.f * w : -2.f * w);
            }
        }
    }
}

// ============================ finalize =====================================
__global__ void finalize_kernel(float* __restrict__ out, int out_size) {
    int b = blockIdx.x * blockDim.x + threadIdx.x;
    if (b >= M_ROWS) return;
    float s = g_s[b];
    float o = 1.0f / (1.0f + expf(-s));
    if (b < out_size) out[b] = o;
    int yi = M_ROWS + b;
    if (yi < out_size) out[yi] = (s >= 0.0f) ? 1.0f : 0.0f;
}

// ============================ launcher =====================================
extern "C" void kernel_launch(void* const* d_in, const int* in_sizes, int n_in,
                              void* d_out, int out_size) {
    const float* X  = (const float*)d_in[0];   // [16384, 4096]
    const float* W1 = (const float*)d_in[1];   // [4096, 4096]
    const float* W2 = (const float*)d_in[2];   // [4096]
    float* out = (float*)d_out;

    cudaFuncSetAttribute(gemm_mma_kernel,
                         cudaFuncAttributeMaxDynamicSharedMemorySize, DYN_SMEM);

    binarize_w1_kernel<<<(N_DIM * (size_t)K_DIM) / (8 * 256), 256>>>(W1);
    split_x_kernel<<<(M_ROWS * (size_t)K_DIM) / (8 * 256), 256>>>(X);

    gemm_mma_kernel<<<(M_ROWS / BM) * (N_DIM / BN), 256, DYN_SMEM>>>(W2);

    correction_kernel<<<1536, 128>>>(X, W1, W2);

    finalize_kernel<<<(M_ROWS + 255) / 256, 256>>>(out, out_size);
}